// round 1
// baseline (speedup 1.0000x reference)
#include <cuda_runtime.h>

// x: (16, 256, 128, 128) fp32 NCHW.
// y = 2 * revcummax_W( revcummax_H( x ) )
//
// One CTA per (n*c) image. 128 threads. Tile staged in padded SMEM
// (pitch 129 floats -> conflict-free for both column- and row-direction
// scalar access, since 129 % 32 == 1).

#define H 128
#define W 128
#define PITCH 129                      // 128 + 1 pad
#define SMEM_BYTES (H * PITCH * 4)     // 66048 B

__global__ void __launch_bounds__(128, 3)
top_left_corner_kernel(const float* __restrict__ x, float* __restrict__ y) {
    extern __shared__ float s[];       // [H][PITCH]
    const int t = threadIdx.x;         // 0..127
    const long long base = (long long)blockIdx.x * (H * W);
    const float* __restrict__ xin = x + base;
    float* __restrict__ yout = y + base;

    // ---- coalesced load: each iteration, 128 threads read one full row ----
    #pragma unroll 8
    for (int h = 0; h < H; ++h) {
        s[h * PITCH + t] = xin[h * W + t];
    }
    __syncthreads();

    // ---- reverse cummax over H: thread t owns column t ----
    {
        float run = s[(H - 1) * PITCH + t];
        #pragma unroll 127
        for (int h = H - 2; h >= 0; --h) {
            float v = s[h * PITCH + t];
            run = fmaxf(run, v);
            s[h * PITCH + t] = run;
        }
    }
    __syncthreads();

    // ---- reverse cummax over W: thread t owns row t ----
    {
        float* row = s + t * PITCH;
        float run = row[W - 1];
        #pragma unroll 127
        for (int w = W - 2; w >= 0; --w) {
            float v = row[w];
            run = fmaxf(run, v);
            row[w] = run;
        }
    }
    __syncthreads();

    // ---- coalesced store, fold the *2 here ----
    #pragma unroll 8
    for (int h = 0; h < H; ++h) {
        yout[h * W + t] = 2.0f * s[h * PITCH + t];
    }
}

extern "C" void kernel_launch(void* const* d_in, const int* in_sizes, int n_in,
                              void* d_out, int out_size) {
    const float* x = (const float*)d_in[0];
    float* y = (float*)d_out;

    // 16 * 256 images of 128x128
    const int n_imgs = in_sizes[0] / (H * W);   // 4096

    cudaFuncSetAttribute(top_left_corner_kernel,
                         cudaFuncAttributeMaxDynamicSharedMemorySize, SMEM_BYTES);
    top_left_corner_kernel<<<n_imgs, 128, SMEM_BYTES>>>(x, y);
}

// round 3
// speedup vs baseline: 1.2516x; 1.2516x over previous
#include <cuda_runtime.h>
#include <cfloat>

// x: (16, 256, 128, 128) fp32 NCHW.  y = 2 * revcummax_W( revcummax_H( x ) )
//
// One CTA per image, 256 threads, two 64-row phases (bottom half first,
// per-column running maxima carried via colmax[] into the top half).
// Smem tile 64 x 129 (33 KB) -> 5 CTAs/SM. All smem access scalar,
// conflict-free at pitch 129.

#define IMG_W 128
#define HH 64                 // rows per phase
#define PITCH 129

__global__ void __launch_bounds__(256, 5)
tlc_kernel(const float* __restrict__ x, float* __restrict__ y) {
    __shared__ float tile[HH * PITCH];   // 33024 B
    __shared__ float colmax[IMG_W];      // 512 B

    const int t = threadIdx.x;
    const long long base = (long long)blockIdx.x * (128 * IMG_W);

    // mappings
    const int col  = t & 127;            // H-scan / IO column (fixed per thread)
    const int hseg = t >> 7;             // 0: local rows 0..31, 1: rows 32..63
    const int wrow = t & 63;             // W-scan row
    const int wseg = t >> 6;             // 0..3 -> cols wseg*32 .. +31
    const int rofs = t >> 7;             // row offset for IO loops

    #pragma unroll
    for (int phase = 1; phase >= 0; --phase) {
        const float* __restrict__ xin  = x + base + phase * (HH * IMG_W);
        float*       __restrict__ yout = y + base + phase * (HH * IMG_W);

        // ---- load 64x128: warp reads 128B rows, conflict-free STS ----
        #pragma unroll 8
        for (int it = 0; it < 32; ++it) {
            int r = 2 * it + rofs;
            tile[r * PITCH + col] = xin[r * IMG_W + col];
        }
        __syncthreads();

        // ---- H-scan: reverse cummax within 32-row segment of column ----
        {
            const int r0 = hseg * 32;
            float run = -FLT_MAX;
            #pragma unroll 8
            for (int j = 31; j >= 0; --j) {
                float v = tile[(r0 + j) * PITCH + col];
                run = fmaxf(run, v);
                tile[(r0 + j) * PITCH + col] = run;
            }
        }
        __syncthreads();

        // ---- H fixup ----
        if (phase == 1) {
            // seg0 (rows 0..31) folds in T1 = total of rows 32..63.
            if (hseg == 0) {
                float F = tile[32 * PITCH + col];   // seg1 total
                float top = F;
                #pragma unroll 8
                for (int j = 31; j >= 0; --j) {
                    float v = fmaxf(tile[j * PITCH + col], F);
                    tile[j * PITCH + col] = v;
                    if (j == 0) top = v;
                }
                colmax[col] = top;  // max of global rows 64..127 for this column
            }
        } else {
            // all 64 rows fold in colmax; seg0 additionally folds seg1 total.
            float cm = colmax[col];
            float T1 = tile[32 * PITCH + col];      // read before any fixup write
            __syncthreads();
            float F = (hseg == 0) ? fmaxf(T1, cm) : cm;
            const int r0 = hseg * 32;
            #pragma unroll 8
            for (int j = 0; j < 32; ++j) {
                float v = tile[(r0 + j) * PITCH + col];
                tile[(r0 + j) * PITCH + col] = fmaxf(v, F);
            }
        }
        __syncthreads();

        // ---- W-scan: reverse cummax within 32-col segment of row ----
        {
            float* row = &tile[wrow * PITCH + wseg * 32];
            float run = -FLT_MAX;
            #pragma unroll 8
            for (int j = 31; j >= 0; --j) {
                float v = row[j];
                run = fmaxf(run, v);
                row[j] = run;
            }
        }
        __syncthreads();

        // ---- store pass: fold W segment-suffix fixup + *2, coalesced STG ----
        // Thread's column (and thus segment) is fixed; per-warp seg is uniform.
        {
            const int seg = col >> 5;
            #pragma unroll 8
            for (int it = 0; it < 32; ++it) {
                int r = 2 * it + rofs;
                const float* trow = &tile[r * PITCH];
                float S = -FLT_MAX;        // suffix max of segment totals right of seg
                if (seg < 3) S = trow[96];              // T3
                if (seg < 2) S = fmaxf(S, trow[64]);    // T2
                if (seg < 1) S = fmaxf(S, trow[32]);    // T1
                float v = trow[col];
                yout[r * IMG_W + col] = 2.0f * fmaxf(v, S);
            }
        }
        __syncthreads();   // protect tile before next phase's load
    }
}

extern "C" void kernel_launch(void* const* d_in, const int* in_sizes, int n_in,
                              void* d_out, int out_size) {
    const float* x = (const float*)d_in[0];
    float* y = (float*)d_out;
    const int n_imgs = in_sizes[0] / (128 * IMG_W);   // 4096
    tlc_kernel<<<n_imgs, 256>>>(x, y);
}

// round 4
// speedup vs baseline: 1.6735x; 1.3371x over previous
#include <cuda_runtime.h>
#include <cfloat>

// x: (16, 256, 128, 128) fp32 NCHW.  y = 2 * revcummax_W( revcummax_H( x ) )
//
// One CTA per image, 256 threads, two 64-row phases (bottom half first,
// per-column maxima carried via colmax[]). H-scan leaves SEGMENT-LOCAL
// scans in the tile; the seg-1 total and colmax are folded per-column in
// the W pass. W reverse-cummax runs in registers (quad scan + warp suffix
// shuffle) fused with the store — the tile is read-only after the H-scan.

#define IMG_W 128
#define HH 64
#define PITCH 132                       // 128 + 4: rows stay 16B-aligned

__device__ __forceinline__ float4 f4max(float4 a, float4 b) {
    a.x = fmaxf(a.x, b.x); a.y = fmaxf(a.y, b.y);
    a.z = fmaxf(a.z, b.z); a.w = fmaxf(a.w, b.w);
    return a;
}

__global__ void __launch_bounds__(256, 5)
tlc_kernel(const float* __restrict__ x, float* __restrict__ y) {
    __shared__ float tile[HH * PITCH];   // 33792 B
    __shared__ float colmax[IMG_W];      // 512 B

    const int t    = threadIdx.x;
    const int lane = t & 31;
    const int wid  = t >> 5;             // 0..7
    const int col  = t & 127;            // H-scan column
    const int hseg = t >> 7;             // 0 or 1
    const long long base = (long long)blockIdx.x * (128 * IMG_W);

    #pragma unroll
    for (int phase = 1; phase >= 0; --phase) {
        const float4* __restrict__ xin4  =
            (const float4*)(x + base + phase * (HH * IMG_W));
        float4* __restrict__ yout4 =
            (float4*)(y + base + phase * (HH * IMG_W));

        // ---- load: float4 LDG -> STS.128, warp w owns rows w, w+8, ... ----
        #pragma unroll
        for (int k = 0; k < 8; ++k) {
            int r = wid + 8 * k;
            float4 v = xin4[r * 32 + lane];
            *(float4*)&tile[r * PITCH + 4 * lane] = v;
        }
        __syncthreads();

        // ---- H-scan: segment-local reverse cummax (32 rows per thread) ----
        {
            const int r0 = hseg * 32;
            float run = -FLT_MAX;
            #pragma unroll
            for (int j = 31; j >= 0; --j) {
                int idx = (r0 + j) * PITCH + col;
                run = fmaxf(run, tile[idx]);
                tile[idx] = run;
            }
            __syncthreads();
            // phase-1 column total (global rows 64..127) -> colmax.
            // Written after the sync; only read in phase 0's W pass, which is
            // separated from here by the end-of-phase __syncthreads.
            if (phase == 1 && hseg == 0) {
                colmax[col] = fmaxf(run, tile[32 * PITCH + col]);
            }
        }

        // ---- W pass fused with store: tile is READ-ONLY here ----
        // One warp per row; lane holds cols 4l..4l+3.
        #pragma unroll
        for (int k = 0; k < 8; ++k) {
            int r = wid * 8 + k;        // warps 0-3: r<32, warps 4-7: r>=32
            float4 v = *(const float4*)&tile[r * PITCH + 4 * lane];

            // fold H fixup per column
            if (phase == 1) {
                if (r < 32) {
                    float4 f = *(const float4*)&tile[32 * PITCH + 4 * lane];
                    v = f4max(v, f);
                }
            } else {
                float4 f = *(const float4*)&colmax[4 * lane];
                if (r < 32) {
                    float4 g = *(const float4*)&tile[32 * PITCH + 4 * lane];
                    f = f4max(f, g);
                }
                v = f4max(v, f);
            }

            // in-quad reverse cummax (x = leftmost col)
            v.z = fmaxf(v.z, v.w);
            v.y = fmaxf(v.y, v.z);
            v.x = fmaxf(v.x, v.y);

            // inclusive suffix-max of quad totals across lanes, then shift
            float s = v.x;
            #pragma unroll
            for (int d = 1; d < 32; d <<= 1) {
                float o = __shfl_down_sync(0xffffffffu, s, d);
                if (lane + d < 32) s = fmaxf(s, o);
            }
            float e = __shfl_down_sync(0xffffffffu, s, 1);
            if (lane == 31) e = -FLT_MAX;

            v.x = 2.0f * fmaxf(v.x, e);
            v.y = 2.0f * fmaxf(v.y, e);
            v.z = 2.0f * fmaxf(v.z, e);
            v.w = 2.0f * fmaxf(v.w, e);

            yout4[r * 32 + lane] = v;
        }
        __syncthreads();   // protect tile + colmax ordering across phases
    }
}

extern "C" void kernel_launch(void* const* d_in, const int* in_sizes, int n_in,
                              void* d_out, int out_size) {
    const float* x = (const float*)d_in[0];
    float* y = (float*)d_out;
    const int n_imgs = in_sizes[0] / (128 * IMG_W);   // 4096
    tlc_kernel<<<n_imgs, 256>>>(x, y);
}